// round 12
// baseline (speedup 1.0000x reference)
#include <cuda_runtime.h>
#include <cuda_fp16.h>
#include <math.h>

#define NX 128
#define NG 64
#define P  8192
#define T_STEPS 4
#define N_ITER 50
#define KAPPA 0.8f
#define LAMDA 0.9f
#define YITA  0.1f
#define NEG_SLOPE 0.01f

#define NBLK 128         // blocks; each owns 64 contiguous columns
#define CPB  64          // columns per block (64 cols * 2B = one 128B line/row)
#define NTHR 1024        // 32 warps/SM

// Device scratch (static __device__ — the sanctioned path)
__device__ __half g_M16[(size_t)P * P];   // 128 MB fp16 copy of M0
__device__ float g_h[P];
__device__ float g_u[3 * P];              // u_s = p+h from earlier timesteps
__device__ float g_v[3 * P];              // v_s = p-h
__device__ float g_dotpart[3 * NBLK];     // per-block partials (dots / loss)
__device__ float g_loss;
__device__ volatile unsigned g_gen;       // grid barrier generation
__device__ unsigned g_count;              // barrier arrivals (0 between barriers)

__device__ __forceinline__ float f_p(float v) {
    float c = fminf(fmaxf(v, -1.0f), 1.0f);
    return (c >= 0.0f) ? c : NEG_SLOPE * c;
}

// L2 access policies (createpolicy + cache_hint form: valid for v4.b32).
__device__ __forceinline__ unsigned long long make_policy_keep() {
    unsigned long long pol;
    asm("createpolicy.fractional.L2::evict_last.b64 %0, 1.0;" : "=l"(pol));
    return pol;
}
__device__ __forceinline__ unsigned long long make_policy_stream() {
    unsigned long long pol;
    asm("createpolicy.fractional.L2::evict_first.b64 %0, 1.0;" : "=l"(pol));
    return pol;
}
__device__ __forceinline__ uint4 ldg_hint(const uint4* p, unsigned long long pol) {
    uint4 r;
    asm("ld.global.nc.L2::cache_hint.v4.b32 {%0,%1,%2,%3}, [%4], %5;"
        : "=r"(r.x), "=r"(r.y), "=r"(r.z), "=r"(r.w) : "l"(p), "l"(pol));
    return r;
}

// Software grid barrier; all NBLK blocks co-resident (128 <= 148 SMs, 1/SM).
__device__ __forceinline__ void grid_barrier() {
    if (threadIdx.x < CPB) __threadfence();   // only tid<64 write globals
    __syncthreads();
    if (threadIdx.x == 0) {
        unsigned my = g_gen;
        if (atomicAdd(&g_count, 1) == NBLK - 1) {
            g_count = 0;
            __threadfence();
            g_gen = my + 1;   // release
        } else {
            while (g_gen == my) __nanosleep(64);
        }
    }
    __syncthreads();
    __threadfence();
}

// Convert M0 fp32 -> fp16 (runs each replay)
__global__ void k_convert(const float* __restrict__ M) {
    size_t i = ((size_t)blockIdx.x * blockDim.x + threadIdx.x) * 8;
    const float4* src = (const float4*)(M + i);
    float4 a = src[0];
    float4 b = src[1];
    __half2 h0 = __floats2half2_rn(a.x, a.y);
    __half2 h1 = __floats2half2_rn(a.z, a.w);
    __half2 h2 = __floats2half2_rn(b.x, b.y);
    __half2 h3 = __floats2half2_rn(b.z, b.w);
    uint4 out;
    out.x = *(unsigned*)&h0;
    out.y = *(unsigned*)&h1;
    out.z = *(unsigned*)&h2;
    out.w = *(unsigned*)&h3;
    *(uint4*)(g_M16 + i) = out;
}

// Persistent per-timestep kernel: init + 50 attractor iterations + loss.
// M_t = lam_pow*M0 + sum_s w_s * outer(u_s, v_s), applied analytically.
// Block b owns columns [b*64, b*64+64); full h staged in smem each iter.
// WARP SPECIALIZATION: warps 0-15 read rows 0..4095 with evict_last
// (64 MB pinned in L2); warps 16-31 read rows 4096..8191 with evict_first
// (64 MB streamed from DRAM). A streaming warp's loads are ALL DRAM misses,
// doubling per-warp DRAM MLP vs the interleaved form; the two classes
// overlap in time on each SM.
__global__ void __launch_bounds__(NTHR, 1)
k_attractor(const float* __restrict__ x, const float* __restrict__ gin,
            float* __restrict__ out, int t,
            float lam_pow, float w0, float w1, float w2) {
    __shared__ float h_sm[P];          // 32 KB full h
    __shared__ float red[CPB][33];     // red[col][warp] partials, padded
    __shared__ float red2[CPB];
    __shared__ float dsum[3][4];       // dot reduce: 4 warp sums per term
    __shared__ float psm[3][2];        // publish reduce: 2 warp sums per term

    const int b    = blockIdx.x;
    const int tid  = threadIdx.x;
    const int lane = tid & 31;
    const int wid  = tid >> 5;         // 0..31
    const int par  = (tid >= 512);     // 0: pinned half, 1: streamed half
    const int q    = (tid >> 3) & 63;  // row lane within half (0..63)
    const int cc   = tid & 7;          // col chunk 0..7
    const int cb0  = b * CPB;
    const int nterms = t;

    const unsigned long long polK = make_policy_keep();
    const unsigned long long polS = make_policy_stream();
    const unsigned long long mypol = par ? polS : polK;

    const int rbase = par * 4096 + q;              // first row of this thread
    const uint4* __restrict__ Mbase4 =
        (const uint4*)(g_M16 + (size_t)rbase * P + cb0 + cc * 8);
    const size_t RSTRIDE = (size_t)64 * P / 8;     // 64-row step in uint4

    // ---- init: h0 = f_p(tile(g_t)) computed locally (no global traffic) ----
    for (int k = tid; k < P; k += NTHR)
        h_sm[k] = f_p(gin[t * NG + (k & (NG - 1))]);
    __syncthreads();

    // ---- prologue: publish dot partials of h0 (only t>0) ----
    if (nterms > 0) {
        if (tid < CPB) {
            int col = cb0 + tid;
            float hv = h_sm[col];
            for (int s = 0; s < nterms; ++s) {
                float w = hv * __ldg(&g_u[s * P + col]);
#pragma unroll
                for (int off = 16; off; off >>= 1)
                    w += __shfl_xor_sync(0xFFFFFFFFu, w, off);
                if (lane == 0) psm[s][wid] = w;
            }
        }
        __syncthreads();
        if (tid == 0)
            for (int s = 0; s < nterms; ++s)
                g_dotpart[s * NBLK + b] = psm[s][0] + psm[s][1];
        grid_barrier();
    }

    float hn_val = 0.f;   // tid<64: this thread's column value of h

    for (int it = 0; it < N_ITER; ++it) {
        // ---- global dots: identical fixed-order value in every block ----
        if (nterms > 0 && tid < NBLK) {
            for (int s = 0; s < nterms; ++s) {
                float a = __ldcg(&g_dotpart[s * NBLK + tid]);
#pragma unroll
                for (int off = 16; off; off >>= 1)
                    a += __shfl_xor_sync(0xFFFFFFFFu, a, off);
                if (lane == 0) dsum[s][wid] = a;
            }
        }

        // ---- refresh full h (it==0: already computed locally) ----
        if (it > 0) {
            for (int i = tid; i < P / 4; i += NTHR)
                ((float4*)h_sm)[i] = __ldcg(((const float4*)g_h) + i);
        }
        __syncthreads();

        float dots[3] = {0.f, 0.f, 0.f};
        for (int s = 0; s < nterms; ++s)
            dots[s] = ((dsum[s][0] + dsum[s][1]) + dsum[s][2]) + dsum[s][3];

        // ---- matvec: 64 stride-64 rows within this thread's half ----
        const uint4* Mp = Mbase4;
        float a0=0.f,a1=0.f,a2=0.f,a3=0.f,a4=0.f,a5=0.f,a6=0.f,a7=0.f;
#pragma unroll 8
        for (int i = 0; i < 64; ++i) {
            uint4 m = ldg_hint(Mp, mypol);
            Mp += RSTRIDE;
            float hv = h_sm[rbase + 64 * i];
            float2 f0 = __half22float2(*(__half2*)&m.x);
            float2 f1 = __half22float2(*(__half2*)&m.y);
            float2 f2 = __half22float2(*(__half2*)&m.z);
            float2 f3 = __half22float2(*(__half2*)&m.w);
            a0 = fmaf(hv, f0.x, a0); a1 = fmaf(hv, f0.y, a1);
            a2 = fmaf(hv, f1.x, a2); a3 = fmaf(hv, f1.y, a3);
            a4 = fmaf(hv, f2.x, a4); a5 = fmaf(hv, f2.y, a5);
            a6 = fmaf(hv, f3.x, a6); a7 = fmaf(hv, f3.y, a7);
        }
        // warp reduce: lanes with same cc combine (4 rows per warp-load)
#pragma unroll
        for (int off = 8; off < 32; off <<= 1) {
            a0 += __shfl_xor_sync(0xFFFFFFFFu, a0, off);
            a1 += __shfl_xor_sync(0xFFFFFFFFu, a1, off);
            a2 += __shfl_xor_sync(0xFFFFFFFFu, a2, off);
            a3 += __shfl_xor_sync(0xFFFFFFFFu, a3, off);
            a4 += __shfl_xor_sync(0xFFFFFFFFu, a4, off);
            a5 += __shfl_xor_sync(0xFFFFFFFFu, a5, off);
            a6 += __shfl_xor_sync(0xFFFFFFFFu, a6, off);
            a7 += __shfl_xor_sync(0xFFFFFFFFu, a7, off);
        }
        if (lane < 8) {
            int c0 = lane * 8;
            red[c0 + 0][wid] = a0; red[c0 + 1][wid] = a1;
            red[c0 + 2][wid] = a2; red[c0 + 3][wid] = a3;
            red[c0 + 4][wid] = a4; red[c0 + 5][wid] = a5;
            red[c0 + 6][wid] = a6; red[c0 + 7][wid] = a7;
        }
        __syncthreads();

        // ---- parallel column reduce: 512 threads, 8 per column ----
        if (tid < 512) {
            int c = tid >> 3, j = tid & 7;
            float s = ((red[c][j * 4] + red[c][j * 4 + 1]) +
                       (red[c][j * 4 + 2] + red[c][j * 4 + 3]));
            s += __shfl_xor_sync(0xFFFFFFFFu, s, 1);
            s += __shfl_xor_sync(0xFFFFFFFFu, s, 2);
            s += __shfl_xor_sync(0xFFFFFFFFu, s, 4);
            if (j == 0) red2[c] = s;
        }
        __syncthreads();

        // ---- rank-1 corrections + pointwise update ----
        if (tid < CPB) {
            int col = cb0 + tid;
            float y = red2[tid] * lam_pow;
            if (nterms > 0) y = fmaf(w0 * dots[0], __ldg(&g_v[0 * P + col]), y);
            if (nterms > 1) y = fmaf(w1 * dots[1], __ldg(&g_v[1 * P + col]), y);
            if (nterms > 2) y = fmaf(w2 * dots[2], __ldg(&g_v[2 * P + col]), y);
            float ho = h_sm[col];
            hn_val = f_p(KAPPA * ho + ho * y);
            g_h[col] = hn_val;
            // publish dot partials of new h (skip after last iteration)
            if (nterms > 0 && it < N_ITER - 1) {
                for (int s = 0; s < nterms; ++s) {
                    float w = hn_val * __ldg(&g_u[s * P + col]);
#pragma unroll
                    for (int off = 16; off; off >>= 1)
                        w += __shfl_xor_sync(0xFFFFFFFFu, w, off);
                    if (lane == 0) psm[s][wid] = w;
                }
            }
        }
        if (nterms > 0 && it < N_ITER - 1) {
            __syncthreads();
            if (tid == 0)
                for (int s = 0; s < nterms; ++s)
                    g_dotpart[s * NBLK + b] = psm[s][0] + psm[s][1];
        }
        grid_barrier();
    }

    // ---- epilogue: loss partial, store u/v, block 0 finalizes ----
    if (tid < CPB) {
        int col = cb0 + tid;
        float p = x[t * NX + (col >> 6)] * gin[t * NG + (col & (NG - 1))];
        float h = hn_val;
        if (t < 3) {
            g_u[t * P + col] = p + h;
            g_v[t * P + col] = p - h;
        }
        float a = fabsf(p - h);
#pragma unroll
        for (int off = 16; off; off >>= 1)
            a += __shfl_xor_sync(0xFFFFFFFFu, a, off);
        if (lane == 0) psm[0][wid] = a;
    }
    __syncthreads();
    if (tid == 0) g_dotpart[b] = psm[0][0] + psm[0][1];
    grid_barrier();

    if (b == 0) {
        if (tid < NBLK) {
            float a = __ldcg(&g_dotpart[tid]);
#pragma unroll
            for (int off = 16; off; off >>= 1)
                a += __shfl_xor_sync(0xFFFFFFFFu, a, off);
            if (lane == 0) dsum[0][wid] = a;
        }
        __syncthreads();
        if (tid == 0) {
            float L = (t == 0 ? 0.f : g_loss) +
                      (((dsum[0][0] + dsum[0][1]) + dsum[0][2]) + dsum[0][3]);
            g_loss = L;
            *out = L;
        }
    }
}

extern "C" void kernel_launch(void* const* d_in, const int* in_sizes, int n_in,
                              void* d_out, int out_size) {
    const float* x = (const float*)d_in[0];   // [4,128]
    const float* g = (const float*)d_in[1];   // [4,64]
    const float* M = (const float*)d_in[2];   // [8192,8192]
    float* out = (float*)d_out;
    (void)in_sizes; (void)n_in; (void)out_size;

    k_convert<<<(int)((size_t)P * P / 8 / 256), 256>>>(M);

    for (int t = 0; t < T_STEPS; ++t) {
        float lam_pow = 1.0f;
        for (int i = 0; i < t; ++i) lam_pow *= LAMDA;
        float w[3] = {0.0f, 0.0f, 0.0f};
        for (int s = 0; s < t; ++s) {
            float lp = 1.0f;
            for (int i = 0; i < t - 1 - s; ++i) lp *= LAMDA;
            w[s] = YITA * lp;
        }
        k_attractor<<<NBLK, NTHR>>>(x, g, out, t, lam_pow, w[0], w[1], w[2]);
    }
}

// round 13
// speedup vs baseline: 1.0482x; 1.0482x over previous
#include <cuda_runtime.h>
#include <cuda_fp16.h>
#include <math.h>

#define NX 128
#define NG 64
#define P  8192
#define T_STEPS 4
#define N_ITER 50
#define KAPPA 0.8f
#define LAMDA 0.9f
#define YITA  0.1f
#define NEG_SLOPE 0.01f

#define NBLK 128         // blocks; each owns 64 contiguous columns
#define CPB  64          // columns per block
#define NTHR 1024        // 32 warps = 2 col-halves x 16 k-slices

// Device scratch (static __device__ — the sanctioned path)
__device__ __half g_M16[(size_t)P * P];   // 128 MB: M0 in mma FRAGMENT order
__device__ float g_h[P];
__device__ float g_u[3 * P];
__device__ float g_v[3 * P];
__device__ float g_dotpart[3 * NBLK];
__device__ float g_loss;
__device__ volatile unsigned g_gen;
__device__ unsigned g_count;

__device__ __forceinline__ float f_p(float v) {
    float c = fminf(fmaxf(v, -1.0f), 1.0f);
    return (c >= 0.0f) ? c : NEG_SLOPE * c;
}

// L2 access policies (createpolicy + cache_hint; valid for v4.b32)
__device__ __forceinline__ unsigned long long make_policy_keep() {
    unsigned long long pol;
    asm("createpolicy.fractional.L2::evict_last.b64 %0, 1.0;" : "=l"(pol));
    return pol;
}
__device__ __forceinline__ unsigned long long make_policy_stream() {
    unsigned long long pol;
    asm("createpolicy.fractional.L2::evict_first.b64 %0, 1.0;" : "=l"(pol));
    return pol;
}
__device__ __forceinline__ uint4 ldg_hint(const uint4* p, unsigned long long pol) {
    uint4 r;
    asm("ld.global.nc.L2::cache_hint.v4.b32 {%0,%1,%2,%3}, [%4], %5;"
        : "=r"(r.x), "=r"(r.y), "=r"(r.z), "=r"(r.w) : "l"(p), "l"(pol));
    return r;
}

// m16n8k16 f16 x f16 -> f32 mma (row.col). A rows replicated: a0=a1, a2=a3.
__device__ __forceinline__ void mma16816(float* d, unsigned p0, unsigned p1,
                                         unsigned b0, unsigned b1) {
    asm volatile(
        "mma.sync.aligned.m16n8k16.row.col.f32.f16.f16.f32 "
        "{%0,%1,%2,%3}, {%4,%5,%6,%7}, {%8,%9}, {%0,%1,%2,%3};"
        : "+f"(d[0]), "+f"(d[1]), "+f"(d[2]), "+f"(d[3])
        : "r"(p0), "r"(p0), "r"(p1), "r"(p1), "r"(b0), "r"(b1));
}

// pack two fp32 -> f16x2 (lo = first arg)
__device__ __forceinline__ unsigned pack_h2(float lo, float hi) {
    unsigned r;
    asm("cvt.rn.f16x2.f32 %0, %1, %2;" : "=r"(r) : "f"(hi), "f"(lo));
    return r;
}

// Software grid barrier; 128 blocks co-resident (1/SM).
__device__ __forceinline__ void grid_barrier() {
    if (threadIdx.x < CPB) __threadfence();
    __syncthreads();
    if (threadIdx.x == 0) {
        unsigned my = g_gen;
        if (atomicAdd(&g_count, 1) == NBLK - 1) {
            g_count = 0;
            __threadfence();
            g_gen = my + 1;
        } else {
            while (g_gen == my) __nanosleep(64);
        }
    }
    __syncthreads();
    __threadfence();
}

// Swizzle M0 (fp32, row-major) into fp16 mma-fragment order (runs each replay).
// Granule (b,e,w,s,tp): 512B = 32 lanes x 16B. Lane l's uint4 =
//   { B[k0+2m .. +1][c0], B[k0+8+2m .. +1][c0],     (ntile 2tp)
//     same two pairs at c1 }                         (ntile 2tp+1)
// with m=l%4, gc=l/4, k0 = 512w+16s, c_u = 64b+32e+8(2tp+u)+gc.
__global__ void k_swizzle(const float* __restrict__ M) {
    __shared__ __half tile[16][32];
    int idx = blockIdx.x;              // b<<10 | e<<9 | w<<5 | s
    int s = idx & 31;
    int w = (idx >> 5) & 15;
    int e = (idx >> 9) & 1;
    int b = idx >> 10;
    int tid = threadIdx.x;             // 64 threads

    int r0 = 512 * w + 16 * s;         // global row of tile row 0
    int c0 = 64 * b + 32 * e;          // global col of tile col 0

    // load 16x32 fp32 tile (each thread: 8 consecutive floats of one row)
    {
        int row = tid >> 2;
        int col8 = (tid & 3) * 8;
        const float4* src = (const float4*)(M + (size_t)(r0 + row) * P + c0 + col8);
        float4 v0 = src[0];
        float4 v1 = src[1];
        tile[row][col8 + 0] = __float2half_rn(v0.x);
        tile[row][col8 + 1] = __float2half_rn(v0.y);
        tile[row][col8 + 2] = __float2half_rn(v0.z);
        tile[row][col8 + 3] = __float2half_rn(v0.w);
        tile[row][col8 + 4] = __float2half_rn(v1.x);
        tile[row][col8 + 5] = __float2half_rn(v1.y);
        tile[row][col8 + 6] = __float2half_rn(v1.z);
        tile[row][col8 + 7] = __float2half_rn(v1.w);
    }
    __syncthreads();

    // assemble fragments
    int tp = tid >> 5;
    int l  = tid & 31;
    int m  = l & 3;
    int gc = l >> 2;
    int ra = 2 * m;
    int ca = 8 * (2 * tp) + gc;
    int cb = 8 * (2 * tp + 1) + gc;

    __half2 hx = __halves2half2(tile[ra][ca], tile[ra + 1][ca]);
    __half2 hy = __halves2half2(tile[ra + 8][ca], tile[ra + 9][ca]);
    __half2 hz = __halves2half2(tile[ra][cb], tile[ra + 1][cb]);
    __half2 hw = __halves2half2(tile[ra + 8][cb], tile[ra + 9][cb]);

    uint4 out;
    out.x = *(unsigned*)&hx; out.y = *(unsigned*)&hy;
    out.z = *(unsigned*)&hz; out.w = *(unsigned*)&hw;
    *(uint4*)((char*)g_M16 + ((size_t)idx * 2 + tp) * 512 + l * 16) = out;
}

// Persistent per-timestep kernel. Warp wid = e*16+wks: col-half e (32 cols),
// k-slice wks (rows [512*wks, +512)). 32 ksteps x 4 mma per warp per iter.
// L2: kstep parity interleave — s even pinned (64 MB), s odd streamed.
__global__ void __launch_bounds__(NTHR, 1)
k_attractor(const float* __restrict__ x, const float* __restrict__ gin,
            float* __restrict__ out, int t,
            float lam_pow, float w0, float w1, float w2) {
    __shared__ float h_sm[P];          // 32 KB full h (fp32)
    __shared__ float red[CPB][17];     // red[col][kslice], padded
    __shared__ float red2[CPB];
    __shared__ float dsum[3][4];
    __shared__ float psm[3][2];

    const int b    = blockIdx.x;
    const int tid  = threadIdx.x;
    const int lane = tid & 31;
    const int wid  = tid >> 5;
    const int e    = wid >> 4;         // col-half
    const int wks  = wid & 15;         // k-slice
    const int m    = lane & 3;
    const int cb0  = b * CPB;
    const int nterms = t;

    const unsigned long long polK = make_policy_keep();
    const unsigned long long polS = make_policy_stream();

    // warp's fragment base: granules (b,e,wks,s,tp), 512B each
    const char* wbase = (const char*)g_M16 +
        ((size_t)((b * 2 + e) * 16 + wks) * 64) * 512 + lane * 16;
    const int k0w = 512 * wks;

    // ---- init: h0 computed locally ----
    for (int k = tid; k < P; k += NTHR)
        h_sm[k] = f_p(gin[t * NG + (k & (NG - 1))]);
    __syncthreads();

    // ---- prologue: dot partials of h0 (t>0) ----
    if (nterms > 0) {
        if (tid < CPB) {
            int col = cb0 + tid;
            float hv = h_sm[col];
            for (int s = 0; s < nterms; ++s) {
                float w = hv * __ldg(&g_u[s * P + col]);
#pragma unroll
                for (int off = 16; off; off >>= 1)
                    w += __shfl_xor_sync(0xFFFFFFFFu, w, off);
                if (lane == 0) psm[s][wid] = w;
            }
        }
        __syncthreads();
        if (tid == 0)
            for (int s = 0; s < nterms; ++s)
                g_dotpart[s * NBLK + b] = psm[s][0] + psm[s][1];
        grid_barrier();
    }

    float hn_val = 0.f;

    for (int it = 0; it < N_ITER; ++it) {
        // ---- global dots (identical fixed-order value everywhere) ----
        if (nterms > 0 && tid < NBLK) {
            for (int s = 0; s < nterms; ++s) {
                float a = __ldcg(&g_dotpart[s * NBLK + tid]);
#pragma unroll
                for (int off = 16; off; off >>= 1)
                    a += __shfl_xor_sync(0xFFFFFFFFu, a, off);
                if (lane == 0) dsum[s][wid] = a;
            }
        }
        // ---- refresh full h ----
        if (it > 0) {
            for (int i = tid; i < P / 4; i += NTHR)
                ((float4*)h_sm)[i] = __ldcg(((const float4*)g_h) + i);
        }
        __syncthreads();

        float dots[3] = {0.f, 0.f, 0.f};
        for (int s = 0; s < nterms; ++s)
            dots[s] = ((dsum[s][0] + dsum[s][1]) + dsum[s][2]) + dsum[s][3];

        // ---- tensor-core matvec: 32 ksteps x (2 LDG + 4 mma) ----
        float d0[4] = {0.f, 0.f, 0.f, 0.f};
        float d1[4] = {0.f, 0.f, 0.f, 0.f};
        float d2[4] = {0.f, 0.f, 0.f, 0.f};
        float d3[4] = {0.f, 0.f, 0.f, 0.f};
#pragma unroll 4
        for (int s = 0; s < 32; ++s) {
            const float* hk = &h_sm[k0w + 16 * s + 2 * m];
            float2 ha = *(const float2*)hk;
            float2 hb = *(const float2*)(hk + 8);
            unsigned p0 = pack_h2(ha.x, ha.y);
            unsigned p1 = pack_h2(hb.x, hb.y);
            unsigned long long pol = (s & 1) ? polS : polK;
            uint4 B0 = ldg_hint((const uint4*)(wbase + (size_t)(s * 2 + 0) * 512), pol);
            uint4 B1 = ldg_hint((const uint4*)(wbase + (size_t)(s * 2 + 1) * 512), pol);
            mma16816(d0, p0, p1, B0.x, B0.y);
            mma16816(d1, p0, p1, B0.z, B0.w);
            mma16816(d2, p0, p1, B1.x, B1.y);
            mma16816(d3, p0, p1, B1.z, B1.w);
        }
        // D rows identical (A replicated); lanes 0-3 carry cols 2m, 2m+1
        if (lane < 4) {
            int cl = e * 32 + 2 * m;
            red[cl + 0 * 8 + 0][wks] = d0[0]; red[cl + 0 * 8 + 1][wks] = d0[1];
            red[cl + 1 * 8 + 0][wks] = d1[0]; red[cl + 1 * 8 + 1][wks] = d1[1];
            red[cl + 2 * 8 + 0][wks] = d2[0]; red[cl + 2 * 8 + 1][wks] = d2[1];
            red[cl + 3 * 8 + 0][wks] = d3[0]; red[cl + 3 * 8 + 1][wks] = d3[1];
        }
        __syncthreads();

        // ---- column reduce over 16 k-slices: 512 threads, 8 per column ----
        if (tid < 512) {
            int c = tid >> 3, j = tid & 7;
            float s2 = red[c][j * 2] + red[c][j * 2 + 1];
            s2 += __shfl_xor_sync(0xFFFFFFFFu, s2, 1);
            s2 += __shfl_xor_sync(0xFFFFFFFFu, s2, 2);
            s2 += __shfl_xor_sync(0xFFFFFFFFu, s2, 4);
            if (j == 0) red2[c] = s2;
        }
        __syncthreads();

        // ---- rank-1 corrections + pointwise update ----
        if (tid < CPB) {
            int col = cb0 + tid;
            float y = red2[tid] * lam_pow;
            if (nterms > 0) y = fmaf(w0 * dots[0], __ldg(&g_v[0 * P + col]), y);
            if (nterms > 1) y = fmaf(w1 * dots[1], __ldg(&g_v[1 * P + col]), y);
            if (nterms > 2) y = fmaf(w2 * dots[2], __ldg(&g_v[2 * P + col]), y);
            float ho = h_sm[col];
            hn_val = f_p(KAPPA * ho + ho * y);
            g_h[col] = hn_val;
            if (nterms > 0 && it < N_ITER - 1) {
                for (int s = 0; s < nterms; ++s) {
                    float w = hn_val * __ldg(&g_u[s * P + col]);
#pragma unroll
                    for (int off = 16; off; off >>= 1)
                        w += __shfl_xor_sync(0xFFFFFFFFu, w, off);
                    if (lane == 0) psm[s][wid] = w;
                }
            }
        }
        if (nterms > 0 && it < N_ITER - 1) {
            __syncthreads();
            if (tid == 0)
                for (int s = 0; s < nterms; ++s)
                    g_dotpart[s * NBLK + b] = psm[s][0] + psm[s][1];
        }
        grid_barrier();
    }

    // ---- epilogue: loss partial, store u/v, block 0 finalizes ----
    if (tid < CPB) {
        int col = cb0 + tid;
        float p = x[t * NX + (col >> 6)] * gin[t * NG + (col & (NG - 1))];
        float h = hn_val;
        if (t < 3) {
            g_u[t * P + col] = p + h;
            g_v[t * P + col] = p - h;
        }
        float a = fabsf(p - h);
#pragma unroll
        for (int off = 16; off; off >>= 1)
            a += __shfl_xor_sync(0xFFFFFFFFu, a, off);
        if (lane == 0) psm[0][wid] = a;
    }
    __syncthreads();
    if (tid == 0) g_dotpart[b] = psm[0][0] + psm[0][1];
    grid_barrier();

    if (b == 0) {
        if (tid < NBLK) {
            float a = __ldcg(&g_dotpart[tid]);
#pragma unroll
            for (int off = 16; off; off >>= 1)
                a += __shfl_xor_sync(0xFFFFFFFFu, a, off);
            if (lane == 0) dsum[0][wid] = a;
        }
        __syncthreads();
        if (tid == 0) {
            float L = (t == 0 ? 0.f : g_loss) +
                      (((dsum[0][0] + dsum[0][1]) + dsum[0][2]) + dsum[0][3]);
            g_loss = L;
            *out = L;
        }
    }
}

extern "C" void kernel_launch(void* const* d_in, const int* in_sizes, int n_in,
                              void* d_out, int out_size) {
    const float* x = (const float*)d_in[0];   // [4,128]
    const float* g = (const float*)d_in[1];   // [4,64]
    const float* M = (const float*)d_in[2];   // [8192,8192]
    float* out = (float*)d_out;
    (void)in_sizes; (void)n_in; (void)out_size;

    k_swizzle<<<128 * 2 * 16 * 32, 64>>>(M);

    for (int t = 0; t < T_STEPS; ++t) {
        float lam_pow = 1.0f;
        for (int i = 0; i < t; ++i) lam_pow *= LAMDA;
        float w[3] = {0.0f, 0.0f, 0.0f};
        for (int s = 0; s < t; ++s) {
            float lp = 1.0f;
            for (int i = 0; i < t - 1 - s; ++i) lp *= LAMDA;
            w[s] = YITA * lp;
        }
        k_attractor<<<NBLK, NTHR>>>(x, g, out, t, lam_pow, w[0], w[1], w[2]);
    }
}